// round 4
// baseline (speedup 1.0000x reference)
#include <cuda_runtime.h>
#include <cuda_fp16.h>
#include <cstdint>

// ---------------------------------------------------------------------------
// out[M,N] = in[M,K] @ W^T + bias,  W = lut[widx].
// M=8192, N=4096, K=4096 fp32.  dequant W->fp16, A->fp16, cp.async +
// ldmatrix + mma.sync.m16n8k16 (fp32 acc).
// R4: CTA 128x256, 256 threads, warp tile 64x64, double-buffered fragments.
// ---------------------------------------------------------------------------

#define M_TOTAL 8192
#define N_TOTAL 4096
#define K_TOTAL 4096

#define BM 128
#define BN 256
#define BK 64                       // halves -> 128 bytes per row
#define STAGES 4
#define NUM_KTILES (K_TOTAL / BK)   // 64

#define ROW_BYTES 128
#define A_STAGE_BYTES (BM * ROW_BYTES)               // 16384
#define B_STAGE_BYTES (BN * ROW_BYTES)               // 32768
#define STAGE_BYTES (A_STAGE_BYTES + B_STAGE_BYTES)  // 49152
#define SMEM_TOTAL (STAGES * STAGE_BYTES)            // 196608

// fp16 scratch (device globals: allocation-free per harness rules)
__device__ __align__(1024) __half g_A[(size_t)M_TOTAL * K_TOTAL];
__device__ __align__(1024) __half g_W[(size_t)N_TOTAL * K_TOTAL];

// ---------------------------------------------------------------------------
// helpers
// ---------------------------------------------------------------------------
__device__ __forceinline__ uint32_t smem_u32(const void* p) {
    uint32_t a;
    asm("{ .reg .u64 t; cvta.to.shared.u64 t, %1; cvt.u32.u64 %0, t; }"
        : "=r"(a) : "l"(p));
    return a;
}
__device__ __forceinline__ void cp_async16(uint32_t dst, const void* src) {
    asm volatile("cp.async.cg.shared.global [%0], [%1], 16;"
                 :: "r"(dst), "l"(src) : "memory");
}
__device__ __forceinline__ void cp_commit() {
    asm volatile("cp.async.commit_group;" ::: "memory");
}
template <int N>
__device__ __forceinline__ void cp_wait() {
    asm volatile("cp.async.wait_group %0;" :: "n"(N) : "memory");
}
__device__ __forceinline__ void ldsm_x4(uint32_t& r0, uint32_t& r1,
                                        uint32_t& r2, uint32_t& r3, uint32_t a) {
    asm volatile("ldmatrix.sync.aligned.m8n8.x4.shared.b16 {%0,%1,%2,%3}, [%4];"
                 : "=r"(r0), "=r"(r1), "=r"(r2), "=r"(r3) : "r"(a));
}
__device__ __forceinline__ void mma16816(float* c, const uint32_t* a,
                                         uint32_t b0, uint32_t b1) {
    asm volatile(
        "mma.sync.aligned.m16n8k16.row.col.f32.f16.f16.f32 "
        "{%0,%1,%2,%3}, {%4,%5,%6,%7}, {%8,%9}, {%0,%1,%2,%3};"
        : "+f"(c[0]), "+f"(c[1]), "+f"(c[2]), "+f"(c[3])
        : "r"(a[0]), "r"(a[1]), "r"(a[2]), "r"(a[3]), "r"(b0), "r"(b1));
}

// ---------------------------------------------------------------------------
// prep kernels
// ---------------------------------------------------------------------------
__global__ void dequant_w_kernel(const int* __restrict__ widx,
                                 const float* __restrict__ lut) {
    __shared__ float slut[256];
    int t = threadIdx.x;
    if (t < 256) slut[t] = lut[t];
    __syncthreads();
    size_t i = (size_t)blockIdx.x * blockDim.x + t;   // one int4 (4 idx) per thread
    int4 v = reinterpret_cast<const int4*>(widx)[i];
    __half2 h0 = __floats2half2_rn(slut[v.x], slut[v.y]);
    __half2 h1 = __floats2half2_rn(slut[v.z], slut[v.w]);
    union { __half2 h[2]; uint2 u; } pk;
    pk.h[0] = h0; pk.h[1] = h1;
    reinterpret_cast<uint2*>(g_W)[i] = pk.u;
}

__global__ void convert_a_kernel(const float* __restrict__ inp) {
    size_t i = (size_t)blockIdx.x * blockDim.x + threadIdx.x;  // one float4/thread
    float4 f = reinterpret_cast<const float4*>(inp)[i];
    __half2 h0 = __floats2half2_rn(f.x, f.y);
    __half2 h1 = __floats2half2_rn(f.z, f.w);
    union { __half2 h[2]; uint2 u; } pk;
    pk.h[0] = h0; pk.h[1] = h1;
    reinterpret_cast<uint2*>(g_A)[i] = pk.u;
}

// ---------------------------------------------------------------------------
// GEMM: 128x256x64 CTA tile, 8 warps, warp tile 64x64, 4-stage cp.async.
// smem rows 128B, 16B-chunk xor swizzle: chunk' = chunk ^ (row & 7).
// ---------------------------------------------------------------------------
__global__ void __launch_bounds__(256, 1) gemm_hmma_kernel(
    float* __restrict__ out, const float* __restrict__ bias) {
    extern __shared__ __align__(1024) char smem[];
    const uint32_t sb = smem_u32(smem);

    const int tid = threadIdx.x;
    const int lane = tid & 31;
    const int wid = tid >> 5;
    const int warp_m = wid & 1;      // 2 m-warps * 64 = 128
    const int warp_n = wid >> 1;     // 4 n-warps * 64 = 256

    const int m0 = blockIdx.y * BM;
    const int n0 = blockIdx.x * BN;

    // ---- cp.async mapping (256 threads):
    // A: 128 rows x 8 chunks = 1024 chunks -> 4/thread (row tid/2, c0=(tid&1)*4)
    // B: 256 rows x 8 chunks = 2048 chunks -> 8/thread (row tid, all chunks)
    const int a_ld_row = tid >> 1;
    const int a_ld_c0 = (tid & 1) * 4;
    const int b_ld_row = tid;
    const __half* gA_row = g_A + (size_t)(m0 + a_ld_row) * K_TOTAL + a_ld_c0 * 8;
    const __half* gW_row = g_W + (size_t)(n0 + b_ld_row) * K_TOTAL;
    uint32_t dstA[4], dstB[8];
    #pragma unroll
    for (int j = 0; j < 4; j++) {
        int c = a_ld_c0 + j;
        dstA[j] = a_ld_row * ROW_BYTES + ((c ^ (a_ld_row & 7)) * 16);
    }
    #pragma unroll
    for (int j = 0; j < 8; j++) {
        dstB[j] = A_STAGE_BYTES + b_ld_row * ROW_BYTES + ((j ^ (b_ld_row & 7)) * 16);
    }

    auto load_stage = [&](int s, int kt) {
        uint32_t base = sb + s * STAGE_BYTES;
        const char* srcA = (const char*)(gA_row + kt * BK);
        const char* srcB = (const char*)(gW_row + kt * BK);
        #pragma unroll
        for (int j = 0; j < 4; j++) cp_async16(base + dstA[j], srcA + j * 16);
        #pragma unroll
        for (int j = 0; j < 8; j++) cp_async16(base + dstB[j], srcB + j * 16);
    };

    // ---- ldmatrix per-lane addressing
    const int a_row = warp_m * 64 + (lane & 15);
    const int b_row = warp_n * 64 + (lane & 15);
    const int ch_hi = lane >> 4;          // 0/1
    const int sw = lane & 7;

    float acc[4][8][4];                    // [mi][ni][frag] = 128 regs
    #pragma unroll
    for (int mi = 0; mi < 4; mi++)
        #pragma unroll
        for (int ni = 0; ni < 8; ni++)
            #pragma unroll
            for (int q = 0; q < 4; q++) acc[mi][ni][q] = 0.f;

    // fragment double buffers
    uint32_t af[2][4][4], bf[2][4][4];

    // ---- prologue: fill pipeline
    #pragma unroll
    for (int s = 0; s < STAGES - 1; s++) {
        load_stage(s, s);
        cp_commit();
    }

    auto load_frags = [&](int buf, uint32_t aBase, uint32_t bBase, int s) {
        const uint32_t chunk = (uint32_t)(2 * s + ch_hi);
        const uint32_t csw = (chunk ^ (uint32_t)sw) * 16;
        #pragma unroll
        for (int mi = 0; mi < 4; mi++) {
            uint32_t addr = aBase + mi * 16 * ROW_BYTES + csw;
            ldsm_x4(af[buf][mi][0], af[buf][mi][1], af[buf][mi][2], af[buf][mi][3], addr);
        }
        #pragma unroll
        for (int bj = 0; bj < 4; bj++) {
            uint32_t addr = bBase + bj * 16 * ROW_BYTES + csw;
            ldsm_x4(bf[buf][bj][0], bf[buf][bj][1], bf[buf][bj][2], bf[buf][bj][3], addr);
        }
    };

    for (int kt = 0; kt < NUM_KTILES; kt++) {
        cp_wait<STAGES - 2>();
        __syncthreads();   // stage kt visible; also fences prior-iter reads

        int nk = kt + STAGES - 1;
        if (nk < NUM_KTILES) load_stage(nk % STAGES, nk);
        cp_commit();       // unconditional: uniform wait_group accounting

        const uint32_t stage = sb + (kt % STAGES) * STAGE_BYTES;
        const uint32_t aBase = stage + a_row * ROW_BYTES;
        const uint32_t bBase = stage + A_STAGE_BYTES + b_row * ROW_BYTES;

        load_frags(0, aBase, bBase, 0);
        #pragma unroll
        for (int s = 0; s < 4; s++) {      // 4 k16 steps in BK=64
            if (s < 3) load_frags((s + 1) & 1, aBase, bBase, s + 1);
            const int cur = s & 1;
            #pragma unroll
            for (int mi = 0; mi < 4; mi++)
                #pragma unroll
                for (int ni = 0; ni < 8; ni++) {
                    int bj = ni >> 1, tb = ni & 1;
                    mma16816(acc[mi][ni], af[cur][mi],
                             bf[cur][bj][tb], bf[cur][bj][2 + tb]);
                }
        }
    }

    // ---- epilogue: acc + bias -> out (fp32)
    const int g = lane >> 2;
    const int t = lane & 3;
    const int col_base = n0 + warp_n * 64;
    #pragma unroll
    for (int ni = 0; ni < 8; ni++) {
        int n = col_base + ni * 8 + 2 * t;
        float b0 = __ldg(&bias[n]);
        float b1 = __ldg(&bias[n + 1]);
        #pragma unroll
        for (int mi = 0; mi < 4; mi++) {
            int m = m0 + warp_m * 64 + mi * 16 + g;
            float2 v0 = make_float2(acc[mi][ni][0] + b0, acc[mi][ni][1] + b1);
            float2 v1 = make_float2(acc[mi][ni][2] + b0, acc[mi][ni][3] + b1);
            *reinterpret_cast<float2*>(out + (size_t)m * N_TOTAL + n) = v0;
            *reinterpret_cast<float2*>(out + (size_t)(m + 8) * N_TOTAL + n) = v1;
        }
    }
}

// ---------------------------------------------------------------------------
// host launcher
// ---------------------------------------------------------------------------
extern "C" void kernel_launch(void* const* d_in, const int* in_sizes, int n_in,
                              void* d_out, int out_size) {
    const float* inp  = (const float*)d_in[0];   // [4,2048,4096] fp32
    const float* lut  = (const float*)d_in[1];   // [256] fp32
    const int*   widx = (const int*)d_in[2];     // [4096,4096] int32
    const float* bias = (const float*)d_in[3];   // [4096] fp32
    float* out = (float*)d_out;                  // [4,2048,4096] fp32

    dequant_w_kernel<<<(int)(((size_t)N_TOTAL * K_TOTAL / 4) / 256), 256>>>(widx, lut);
    convert_a_kernel<<<(int)(((size_t)M_TOTAL * K_TOTAL / 4) / 256), 256>>>(inp);

    static bool attr_set = false;
    if (!attr_set) {
        cudaFuncSetAttribute(gemm_hmma_kernel,
                             cudaFuncAttributeMaxDynamicSharedMemorySize, SMEM_TOTAL);
        attr_set = true;
    }
    dim3 grid(N_TOTAL / BN, M_TOTAL / BM, 1);    // (16, 64)
    gemm_hmma_kernel<<<grid, 256, SMEM_TOTAL>>>(out, bias);
}

// round 5
// speedup vs baseline: 1.4302x; 1.4302x over previous
#include <cuda_runtime.h>
#include <cuda_fp16.h>
#include <cstdint>

// ---------------------------------------------------------------------------
// out[M,N] = in[M,K] @ W^T + bias,  W = lut[widx].
// M=8192, N=4096, K=4096 fp32.  dequant W->fp16, A->fp16, cp.async +
// ldmatrix + mma.sync.m16n8k16 (fp32 acc).
// R5: R3 shape (512 thr, warp 64x32) + double-buffered fragment pipeline.
// ---------------------------------------------------------------------------

#define M_TOTAL 8192
#define N_TOTAL 4096
#define K_TOTAL 4096

#define BM 128
#define BN 256
#define BK 64                       // halves -> 128 bytes per row
#define STAGES 4
#define NUM_KTILES (K_TOTAL / BK)   // 64

#define ROW_BYTES 128
#define A_STAGE_BYTES (BM * ROW_BYTES)               // 16384
#define B_STAGE_BYTES (BN * ROW_BYTES)               // 32768
#define STAGE_BYTES (A_STAGE_BYTES + B_STAGE_BYTES)  // 49152
#define SMEM_TOTAL (STAGES * STAGE_BYTES)            // 196608

// fp16 scratch (device globals: allocation-free per harness rules)
__device__ __align__(1024) __half g_A[(size_t)M_TOTAL * K_TOTAL];
__device__ __align__(1024) __half g_W[(size_t)N_TOTAL * K_TOTAL];

// ---------------------------------------------------------------------------
// helpers
// ---------------------------------------------------------------------------
__device__ __forceinline__ uint32_t smem_u32(const void* p) {
    uint32_t a;
    asm("{ .reg .u64 t; cvta.to.shared.u64 t, %1; cvt.u32.u64 %0, t; }"
        : "=r"(a) : "l"(p));
    return a;
}
__device__ __forceinline__ void cp_async16(uint32_t dst, const void* src) {
    asm volatile("cp.async.cg.shared.global [%0], [%1], 16;"
                 :: "r"(dst), "l"(src) : "memory");
}
__device__ __forceinline__ void cp_commit() {
    asm volatile("cp.async.commit_group;" ::: "memory");
}
template <int N>
__device__ __forceinline__ void cp_wait() {
    asm volatile("cp.async.wait_group %0;" :: "n"(N) : "memory");
}
__device__ __forceinline__ void ldsm_x4(uint32_t& r0, uint32_t& r1,
                                        uint32_t& r2, uint32_t& r3, uint32_t a) {
    asm volatile("ldmatrix.sync.aligned.m8n8.x4.shared.b16 {%0,%1,%2,%3}, [%4];"
                 : "=r"(r0), "=r"(r1), "=r"(r2), "=r"(r3) : "r"(a));
}
__device__ __forceinline__ void mma16816(float* c, const uint32_t* a,
                                         uint32_t b0, uint32_t b1) {
    asm volatile(
        "mma.sync.aligned.m16n8k16.row.col.f32.f16.f16.f32 "
        "{%0,%1,%2,%3}, {%4,%5,%6,%7}, {%8,%9}, {%0,%1,%2,%3};"
        : "+f"(c[0]), "+f"(c[1]), "+f"(c[2]), "+f"(c[3])
        : "r"(a[0]), "r"(a[1]), "r"(a[2]), "r"(a[3]), "r"(b0), "r"(b1));
}

// ---------------------------------------------------------------------------
// prep kernels
// ---------------------------------------------------------------------------
__global__ void dequant_w_kernel(const int* __restrict__ widx,
                                 const float* __restrict__ lut) {
    __shared__ float slut[256];
    int t = threadIdx.x;
    if (t < 256) slut[t] = lut[t];
    __syncthreads();
    size_t i = (size_t)blockIdx.x * blockDim.x + t;   // one int4 (4 idx) per thread
    int4 v = reinterpret_cast<const int4*>(widx)[i];
    __half2 h0 = __floats2half2_rn(slut[v.x], slut[v.y]);
    __half2 h1 = __floats2half2_rn(slut[v.z], slut[v.w]);
    union { __half2 h[2]; uint2 u; } pk;
    pk.h[0] = h0; pk.h[1] = h1;
    reinterpret_cast<uint2*>(g_W)[i] = pk.u;
}

__global__ void convert_a_kernel(const float* __restrict__ inp) {
    size_t i = (size_t)blockIdx.x * blockDim.x + threadIdx.x;  // one float4/thread
    float4 f = reinterpret_cast<const float4*>(inp)[i];
    __half2 h0 = __floats2half2_rn(f.x, f.y);
    __half2 h1 = __floats2half2_rn(f.z, f.w);
    union { __half2 h[2]; uint2 u; } pk;
    pk.h[0] = h0; pk.h[1] = h1;
    reinterpret_cast<uint2*>(g_A)[i] = pk.u;
}

// ---------------------------------------------------------------------------
// GEMM: 128x256x64 CTA tile, 16 warps (warp 64x32), 4-stage cp.async,
// k-step software pipeline with double-buffered ldmatrix fragments.
// smem rows 128B, 16B-chunk xor swizzle: chunk' = chunk ^ (row & 7).
// ---------------------------------------------------------------------------
__global__ void __launch_bounds__(512, 1) gemm_hmma_kernel(
    float* __restrict__ out, const float* __restrict__ bias) {
    extern __shared__ __align__(1024) char smem[];
    const uint32_t sb = smem_u32(smem);

    const int tid = threadIdx.x;
    const int lane = tid & 31;
    const int wid = tid >> 5;
    const int warp_m = wid & 1;      // 2 m-warps * 64 = 128
    const int warp_n = wid >> 1;     // 8 n-warps * 32 = 256

    const int m0 = blockIdx.y * BM;
    const int n0 = blockIdx.x * BN;

    // ---- cp.async mapping (512 threads):
    // A: 128 rows x 8 chunks = 1024 chunks -> 2/thread (row tid/4, c0=(tid&3)*2)
    // B: 256 rows x 8 chunks = 2048 chunks -> 4/thread (row tid/2, c0=(tid&1)*4)
    const int a_ld_row = tid >> 2;
    const int a_ld_c0 = (tid & 3) * 2;
    const int b_ld_row = tid >> 1;
    const int b_ld_c0 = (tid & 1) * 4;
    const __half* gA_row = g_A + (size_t)(m0 + a_ld_row) * K_TOTAL + a_ld_c0 * 8;
    const __half* gW_row = g_W + (size_t)(n0 + b_ld_row) * K_TOTAL + b_ld_c0 * 8;
    uint32_t dstA[2], dstB[4];
    #pragma unroll
    for (int j = 0; j < 2; j++) {
        int c = a_ld_c0 + j;
        dstA[j] = a_ld_row * ROW_BYTES + ((c ^ (a_ld_row & 7)) * 16);
    }
    #pragma unroll
    for (int j = 0; j < 4; j++) {
        int c = b_ld_c0 + j;
        dstB[j] = A_STAGE_BYTES + b_ld_row * ROW_BYTES + ((c ^ (b_ld_row & 7)) * 16);
    }

    auto load_stage = [&](int s, int kt) {
        uint32_t base = sb + s * STAGE_BYTES;
        const char* srcA = (const char*)(gA_row + kt * BK);
        const char* srcB = (const char*)(gW_row + kt * BK);
        #pragma unroll
        for (int j = 0; j < 2; j++) cp_async16(base + dstA[j], srcA + j * 16);
        #pragma unroll
        for (int j = 0; j < 4; j++) cp_async16(base + dstB[j], srcB + j * 16);
    };

    // ---- ldmatrix per-lane addressing
    const int a_row = warp_m * 64 + (lane & 15);
    const int b_row = warp_n * 32 + (lane & 15);
    const int ch_hi = lane >> 4;          // 0/1
    const int sw = lane & 7;

    float acc[4][4][4];                    // 64 regs
    #pragma unroll
    for (int mi = 0; mi < 4; mi++)
        #pragma unroll
        for (int ni = 0; ni < 4; ni++)
            #pragma unroll
            for (int q = 0; q < 4; q++) acc[mi][ni][q] = 0.f;

    uint32_t af[2][4][4];                  // 32 regs
    uint32_t bf[2][2][4];                  // 16 regs

    // frag loader: step s of the stage whose bases are (aBase,bBase)
    auto load_frags = [&](int buf, uint32_t aBase, uint32_t bBase, int s) {
        const uint32_t chunk = (uint32_t)(2 * s + ch_hi);
        const uint32_t csw = (chunk ^ (uint32_t)sw) * 16;
        #pragma unroll
        for (int mi = 0; mi < 4; mi++) {
            uint32_t addr = aBase + mi * 16 * ROW_BYTES + csw;
            ldsm_x4(af[buf][mi][0], af[buf][mi][1], af[buf][mi][2], af[buf][mi][3], addr);
        }
        #pragma unroll
        for (int bj = 0; bj < 2; bj++) {
            uint32_t addr = bBase + bj * 16 * ROW_BYTES + csw;
            ldsm_x4(bf[buf][bj][0], bf[buf][bj][1], bf[buf][bj][2], bf[buf][bj][3], addr);
        }
    };
    auto do_mma = [&](int buf) {
        #pragma unroll
        for (int mi = 0; mi < 4; mi++)
            #pragma unroll
            for (int ni = 0; ni < 4; ni++) {
                int bj = ni >> 1, tb = ni & 1;
                mma16816(acc[mi][ni], af[buf][mi], bf[buf][bj][tb], bf[buf][bj][2 + tb]);
            }
    };

    // ---- prologue: fill stages 0..2
    #pragma unroll
    for (int s = 0; s < STAGES - 1; s++) {
        load_stage(s, s);
        cp_commit();
    }
    cp_wait<STAGES - 2>();
    __syncthreads();
    {
        uint32_t st0a = sb + a_row * ROW_BYTES;
        uint32_t st0b = sb + A_STAGE_BYTES + b_row * ROW_BYTES;
        load_frags(0, st0a, st0b, 0);      // step 0 of ktile 0
    }

    for (int kt = 0; kt < NUM_KTILES; kt++) {
        const uint32_t stage = sb + (kt & (STAGES - 1)) * STAGE_BYTES;
        const uint32_t aBase = stage + a_row * ROW_BYTES;
        const uint32_t bBase = stage + A_STAGE_BYTES + b_row * ROW_BYTES;

        load_frags(1, aBase, bBase, 1);
        do_mma(0);

        // refill the slot we finished reading in ktile kt-1 with ktile kt+3.
        // sync: every warp finished its last LDSM of that slot back in kt-1.
        __syncthreads();
        {
            int nk = kt + STAGES - 1;
            if (nk < NUM_KTILES) load_stage(nk & (STAGES - 1), nk);
            cp_commit();   // unconditional: uniform wait_group accounting
        }

        load_frags(0, aBase, bBase, 2);
        do_mma(1);
        load_frags(1, aBase, bBase, 3);
        do_mma(0);

        // stage kt+1 ready + visible, then prefetch its step-0 fragments
        cp_wait<STAGES - 2>();
        __syncthreads();
        {
            const uint32_t nstage = sb + ((kt + 1) & (STAGES - 1)) * STAGE_BYTES;
            load_frags(0, nstage + a_row * ROW_BYTES,
                       nstage + A_STAGE_BYTES + b_row * ROW_BYTES, 0);
        }
        do_mma(1);
    }

    // ---- epilogue: acc + bias -> out (fp32)
    const int g = lane >> 2;
    const int t = lane & 3;
    const int col_base = n0 + warp_n * 32;
    #pragma unroll
    for (int ni = 0; ni < 4; ni++) {
        int n = col_base + ni * 8 + 2 * t;
        float b0 = __ldg(&bias[n]);
        float b1 = __ldg(&bias[n + 1]);
        #pragma unroll
        for (int mi = 0; mi < 4; mi++) {
            int m = m0 + warp_m * 64 + mi * 16 + g;
            float2 v0 = make_float2(acc[mi][ni][0] + b0, acc[mi][ni][1] + b1);
            float2 v1 = make_float2(acc[mi][ni][2] + b0, acc[mi][ni][3] + b1);
            *reinterpret_cast<float2*>(out + (size_t)m * N_TOTAL + n) = v0;
            *reinterpret_cast<float2*>(out + (size_t)(m + 8) * N_TOTAL + n) = v1;
        }
    }
}

// ---------------------------------------------------------------------------
// host launcher
// ---------------------------------------------------------------------------
extern "C" void kernel_launch(void* const* d_in, const int* in_sizes, int n_in,
                              void* d_out, int out_size) {
    const float* inp  = (const float*)d_in[0];   // [4,2048,4096] fp32
    const float* lut  = (const float*)d_in[1];   // [256] fp32
    const int*   widx = (const int*)d_in[2];     // [4096,4096] int32
    const float* bias = (const float*)d_in[3];   // [4096] fp32
    float* out = (float*)d_out;                  // [4,2048,4096] fp32

    dequant_w_kernel<<<(int)(((size_t)N_TOTAL * K_TOTAL / 4) / 256), 256>>>(widx, lut);
    convert_a_kernel<<<(int)(((size_t)M_TOTAL * K_TOTAL / 4) / 256), 256>>>(inp);

    static bool attr_set = false;
    if (!attr_set) {
        cudaFuncSetAttribute(gemm_hmma_kernel,
                             cudaFuncAttributeMaxDynamicSharedMemorySize, SMEM_TOTAL);
        attr_set = true;
    }
    dim3 grid(N_TOTAL / BN, M_TOTAL / BM, 1);    // (16, 64)
    gemm_hmma_kernel<<<grid, 512, SMEM_TOTAL>>>(out, bias);
}